// round 1
// baseline (speedup 1.0000x reference)
#include <cuda_runtime.h>
#include <math.h>

// Problem constants
#define Bb   8
#define Tt   128
#define Nn   512
#define HIDc 4
#define Dd   2048
#define Ee   16384
#define FD   8192
#define NEG  0.2f

// ---------------- device scratch (no allocations allowed) ----------------
__device__ __align__(256) float g_seq[1024 * 2048];   // [T*B, D] GAT output, 8 MB
__device__ __align__(256) float g_zx[1024u * 8192u];  // [T*B, 4D] x@Wih^T + bias, 32 MB
__device__ __align__(256) float g_h[2][Bb * Dd];      // double-buffered hidden
__device__ __align__(256) float g_c[Bb * Dd];         // cell state
__device__ int   g_deg[Nn];
__device__ int   g_off[Nn];
__device__ int   g_cur[Nn];
__device__ int   g_csr[Ee];
__device__ float g_cs, g_cd;

// ---------------- f32x2 packed FMA helpers (sm_100+) ----------------
typedef unsigned long long ull;

__device__ __forceinline__ ull pk2(float x, float y) {
    ull r;
    asm("mov.b64 %0, {%1, %2};" : "=l"(r) : "f"(x), "f"(y));
    return r;
}
__device__ __forceinline__ void ffma2(ull &d, ull a, ull b) {
    asm("fma.rn.f32x2 %0, %1, %2, %0;" : "+l"(d) : "l"(a), "l"(b));
}
__device__ __forceinline__ float fsum2(ull v) {
    float x, y;
    asm("mov.b64 {%0, %1}, %2;" : "=f"(x), "=f"(y) : "l"(v));
    return x + y;
}
__device__ __forceinline__ void upk2(ull v, float &x, float &y) {
    asm("mov.b64 {%0, %1}, %2;" : "=f"(x), "=f"(y) : "l"(v));
}

// ---------------- GAT preprocessing ----------------
__global__ void k_prep(const float* __restrict__ W, const float* __restrict__ as_,
                       const float* __restrict__ ad_) {
    int i = blockIdx.x * blockDim.x + threadIdx.x;
    if (i < Nn) g_deg[i] = 0;
    if (i == 0) {
        float cs = 0.f, cd = 0.f;
        for (int k = 0; k < HIDc; k++) { cs += W[k] * as_[k]; cd += W[k] * ad_[k]; }
        g_cs = cs; g_cd = cd;
    }
}

__global__ void k_deg(const int* __restrict__ ei) {
    int e = blockIdx.x * 256 + threadIdx.x;
    if (e < Ee) atomicAdd(&g_deg[ei[Ee + e]], 1);
}

__global__ void k_scan() {
    __shared__ int s[Nn];
    int i = threadIdx.x;
    int d = g_deg[i];
    s[i] = d;
    __syncthreads();
    for (int off = 1; off < Nn; off <<= 1) {
        int t = 0;
        if (i >= off) t = s[i - off];
        __syncthreads();
        s[i] += t;
        __syncthreads();
    }
    g_off[i] = s[i] - d;
    g_cur[i] = s[i] - d;
}

__global__ void k_fill(const int* __restrict__ ei) {
    int e = blockIdx.x * 256 + threadIdx.x;
    if (e < Ee) {
        int src = ei[e];
        int dst = ei[Ee + e];
        int pos = atomicAdd(&g_cur[dst], 1);
        g_csr[pos] = src;
    }
}

// GAT for batch-0 nodes (the only ones with real incoming edges). One block per t.
__global__ void k_gat_b0(const float* __restrict__ x, const float* __restrict__ W,
                         const float* __restrict__ bias) {
    __shared__ float xs[Nn];
    int t = blockIdx.x;
    int i = threadIdx.x;
    xs[i] = x[t * Nn + i];   // batch 0: (0*T + t)*N + i
    __syncthreads();
    float cs = g_cs, cd = g_cd;
    float xi = xs[i];
    float es = xi * (cs + cd);
    es = es > 0.f ? es : NEG * es;          // self-loop logit
    int beg = g_off[i], end = beg + g_deg[i];
    float m = es;
    for (int e = beg; e < end; e++) {
        float v = cs * xs[g_csr[e]] + cd * xi;
        v = v > 0.f ? v : NEG * v;
        m = fmaxf(m, v);
    }
    float den = expf(es - m);
    float ssum = den * xi;
    for (int e = beg; e < end; e++) {
        float xsrc = xs[g_csr[e]];
        float v = cs * xsrc + cd * xi;
        v = v > 0.f ? v : NEG * v;
        float w = expf(v - m);
        den += w;
        ssum += w * xsrc;
    }
    float s = ssum / den;
    float* o = &g_seq[(size_t)(t * Bb + 0) * Dd + i * HIDc];
#pragma unroll
    for (int k = 0; k < HIDc; k++) {
        float g = fmaf(s, W[k], bias[k]);
        o[k] = g > 0.f ? g : 0.f;
    }
}

// GAT for batches 1..7: self-loop only => s = x
__global__ void k_gat_rest(const float* __restrict__ x, const float* __restrict__ W,
                           const float* __restrict__ bias) {
    int idx = blockIdx.x * 256 + threadIdx.x;
    if (idx >= Tt * (Bb - 1) * Nn) return;
    int t = idx / ((Bb - 1) * Nn);
    int r = idx - t * (Bb - 1) * Nn;
    int b = 1 + (r >> 9);
    int n = r & (Nn - 1);
    float xi = x[((size_t)b * Tt + t) * Nn + n];
    float* o = &g_seq[(size_t)(t * Bb + b) * Dd + n * HIDc];
#pragma unroll
    for (int k = 0; k < HIDc; k++) {
        float g = fmaf(xi, W[k], bias[k]);
        o[k] = g > 0.f ? g : 0.f;
    }
}

// ---------------- input GEMM: Zx[1024,8192] = seq @ w_ih^T + (b_ih+b_hh) ----------------
// TN layout (both operands K-contiguous), 128x128x16 tiles, 8x8 microtile, f32x2 FMA.
__global__ void __launch_bounds__(256, 2)
k_zx(const float* __restrict__ Bw, const float* __restrict__ bih,
     const float* __restrict__ bhh) {
    __shared__ __align__(16) float As[16][132];
    __shared__ __align__(16) float Bs[16][132];
    int tid = threadIdx.x;
    int lr = tid >> 2;            // 0..63
    int lk = (tid & 3) * 4;       // 0,4,8,12
    int bm = blockIdx.y * 128;
    int bn = blockIdx.x * 128;
    const float* Ap = g_seq + (size_t)(bm + lr) * Dd + lk;
    const float* Bp = Bw + (size_t)(bn + lr) * Dd + lk;
    int tx = tid & 15, ty = tid >> 4;

    ull acc[8][4];
#pragma unroll
    for (int i = 0; i < 8; i++)
#pragma unroll
        for (int j = 0; j < 4; j++) acc[i][j] = pk2(0.f, 0.f);

    for (int k0 = 0; k0 < Dd; k0 += 16) {
#pragma unroll
        for (int hh = 0; hh < 2; hh++) {
            float4 va = *(const float4*)(Ap + (size_t)hh * 64 * Dd + k0);
            As[lk + 0][lr + hh * 64] = va.x;
            As[lk + 1][lr + hh * 64] = va.y;
            As[lk + 2][lr + hh * 64] = va.z;
            As[lk + 3][lr + hh * 64] = va.w;
            float4 vb = *(const float4*)(Bp + (size_t)hh * 64 * Dd + k0);
            Bs[lk + 0][lr + hh * 64] = vb.x;
            Bs[lk + 1][lr + hh * 64] = vb.y;
            Bs[lk + 2][lr + hh * 64] = vb.z;
            Bs[lk + 3][lr + hh * 64] = vb.w;
        }
        __syncthreads();
#pragma unroll
        for (int kk = 0; kk < 16; kk++) {
            float4 a0 = *(const float4*)(&As[kk][ty * 8]);
            float4 a1 = *(const float4*)(&As[kk][ty * 8 + 4]);
            ulonglong2 b0 = *(const ulonglong2*)(&Bs[kk][tx * 8]);
            ulonglong2 b1 = *(const ulonglong2*)(&Bs[kk][tx * 8 + 4]);
            float av[8] = {a0.x, a0.y, a0.z, a0.w, a1.x, a1.y, a1.z, a1.w};
#pragma unroll
            for (int i = 0; i < 8; i++) {
                ull ad = pk2(av[i], av[i]);
                ffma2(acc[i][0], ad, b0.x);
                ffma2(acc[i][1], ad, b0.y);
                ffma2(acc[i][2], ad, b1.x);
                ffma2(acc[i][3], ad, b1.y);
            }
        }
        __syncthreads();
    }
    // store with bias folded in
#pragma unroll
    for (int i = 0; i < 8; i++) {
        int row = bm + ty * 8 + i;
        float* Crow = g_zx + (size_t)row * FD + bn + tx * 8;
#pragma unroll
        for (int jj = 0; jj < 4; jj++) {
            float c0, c1;
            upk2(acc[i][jj], c0, c1);
            int col = bn + tx * 8 + 2 * jj;
            Crow[2 * jj]     = c0 + bih[col]     + bhh[col];
            Crow[2 * jj + 1] = c1 + bih[col + 1] + bhh[col + 1];
        }
    }
}

// ---------------- LSTM init ----------------
__global__ void k_h0() {
    int i = blockIdx.x * 256 + threadIdx.x;
    if (i < Bb * Dd) { g_h[0][i] = 0.f; g_c[i] = 0.f; }
}

// ---------------- one LSTM step: z = Zx[t] + h @ w_hh^T, fused gates ----------------
// 128 blocks x 256 threads. Block owns d-tile of 16 => 64 w_hh rows (4 gates x 16 d).
// Thread (rowi, q): full-K dots of row j for batches q and q+4.
__global__ void __launch_bounds__(256)
k_step(const float* __restrict__ whh, int t, int par) {
    __shared__ __align__(16) float hs[8][516];
    __shared__ float zred[64][9];
    const float* h_in = g_h[par];
    float* h_out = g_h[par ^ 1];
    int tid = threadIdx.x;
    int rowi = tid >> 2;            // 0..63
    int q = tid & 3;                // batch pair selector
    int g = rowi >> 4;              // gate
    int dd = rowi & 15;
    int d0 = blockIdx.x * 16;
    int j = g * Dd + d0 + dd;
    const float* wr = whh + (size_t)j * Dd;

    ull a0 = pk2(0.f, 0.f), a1 = a0, b0 = a0, b1 = a0;

    for (int kc0 = 0; kc0 < Dd; kc0 += 512) {
        // cooperative load of h chunk [8][512]
#pragma unroll
        for (int u = 0; u < 4; u++) {
            int fi = tid + u * 256;           // float4 index 0..1023
            int bb = fi >> 7;                 // 128 float4 per row
            int kk = (fi & 127) << 2;
            float4 v = *(const float4*)(h_in + (size_t)bb * Dd + kc0 + kk);
            *(float4*)(&hs[bb][kk]) = v;
        }
        __syncthreads();
        const float* wc = wr + kc0;
#pragma unroll 4
        for (int kk = 0; kk < 512; kk += 4) {
            ulonglong2 w  = *(const ulonglong2*)(wc + kk);
            ulonglong2 ha = *(const ulonglong2*)(&hs[q][kk]);
            ulonglong2 hb = *(const ulonglong2*)(&hs[q + 4][kk]);
            ffma2(a0, w.x, ha.x);
            ffma2(a1, w.y, ha.y);
            ffma2(b0, w.x, hb.x);
            ffma2(b1, w.y, hb.y);
        }
        __syncthreads();
    }
    zred[rowi][q]     = fsum2(a0) + fsum2(a1);
    zred[rowi][q + 4] = fsum2(b0) + fsum2(b1);
    __syncthreads();

    if (tid < 128) {
        int dd2 = tid >> 3;         // 0..15
        int bb = tid & 7;
        const float* zx = g_zx + (size_t)(t * Bb + bb) * FD + d0 + dd2;
        float zi = zred[0 * 16 + dd2][bb] + zx[0];
        float zf = zred[1 * 16 + dd2][bb] + zx[Dd];
        float zg = zred[2 * 16 + dd2][bb] + zx[2 * Dd];
        float zo = zred[3 * 16 + dd2][bb] + zx[3 * Dd];
        float ig = 1.f / (1.f + expf(-zi));
        float fg = 1.f / (1.f + expf(-zf));
        float gg = tanhf(zg);
        float og = 1.f / (1.f + expf(-zo));
        int idx = bb * Dd + d0 + dd2;
        float cn = fg * g_c[idx] + ig * gg;
        g_c[idx] = cn;
        h_out[idx] = og * tanhf(cn);
    }
}

// ---------------- final linear: out[8,512] = hT @ w_lin^T + b_lin ----------------
__global__ void k_out(const float* __restrict__ wlin, const float* __restrict__ blin,
                      float* __restrict__ out) {
    int idx = blockIdx.x * 256 + threadIdx.x;
    if (idx >= Bb * Nn) return;
    int bb = idx >> 9;
    int o = idx & 511;
    const float* h = g_h[0] + (size_t)bb * Dd;
    const float* w = wlin + (size_t)o * Dd;
    float acc = 0.f;
    for (int d = 0; d < Dd; d += 4) {
        float4 hv = *(const float4*)(h + d);
        float4 wv = *(const float4*)(w + d);
        acc += hv.x * wv.x + hv.y * wv.y + hv.z * wv.z + hv.w * wv.w;
    }
    out[bb * Nn + o] = acc + blin[o];
}

// ---------------- launch ----------------
extern "C" void kernel_launch(void* const* d_in, const int* in_sizes, int n_in,
                              void* d_out, int out_size) {
    const float* x    = (const float*)d_in[0];
    const float* gw   = (const float*)d_in[1];
    const float* as_  = (const float*)d_in[2];
    const float* ad_  = (const float*)d_in[3];
    const float* gb   = (const float*)d_in[4];
    const float* wih  = (const float*)d_in[5];
    const float* whh  = (const float*)d_in[6];
    const float* bih  = (const float*)d_in[7];
    const float* bhh  = (const float*)d_in[8];
    const float* wlin = (const float*)d_in[9];
    const float* blin = (const float*)d_in[10];
    const int*   ei   = (const int*)d_in[11];
    (void)in_sizes; (void)n_in; (void)out_size; (void)wih;

    // GAT preprocessing + CSR build (rebuilt every call: deterministic, cheap)
    k_prep<<<2, 256>>>(gw, as_, ad_);
    k_deg<<<64, 256>>>(ei);
    k_scan<<<1, 512>>>();
    k_fill<<<64, 256>>>(ei);

    // GAT -> g_seq [1024, 2048]
    k_gat_b0<<<Tt, Nn>>>(x, gw, gb);
    k_gat_rest<<<1792, 256>>>(x, gw, gb);

    // Input projection for all timesteps: g_zx = g_seq @ w_ih^T + (b_ih+b_hh)
    {
        dim3 grid(64, 8);
        k_zx<<<grid, 256>>>(wih, bih, bhh);
    }

    // LSTM recurrence
    k_h0<<<64, 256>>>();
    for (int t = 0; t < Tt; t++) {
        k_step<<<128, 256>>>(whh, t, t & 1);
    }

    // Final linear
    k_out<<<16, 256>>>(wlin, blin, (float*)d_out);
}

// round 2
// speedup vs baseline: 1.3241x; 1.3241x over previous
#include <cuda_runtime.h>
#include <math.h>

// Problem constants
#define Bb   8
#define Tt   128
#define Nn   512
#define HIDc 4
#define Dd   2048
#define Ee   16384
#define FD   8192
#define NEG  0.2f

// ---------------- device scratch (no allocations allowed) ----------------
__device__ __align__(256) float g_seq[1024 * 2048];   // [T*B, D] GAT output, 8 MB
__device__ __align__(256) float g_zx[1024u * 8192u];  // [T*B, 4D] x@Wih^T + bias, 32 MB
__device__ __align__(256) float g_h[2][Bb * Dd];      // double-buffered hidden
__device__ __align__(256) float g_c[Bb * Dd];         // cell state
__device__ int   g_deg[Nn];
__device__ int   g_off[Nn];
__device__ int   g_cur[Nn];
__device__ int   g_csr[Ee];
__device__ float g_cs, g_cd;

// ---------------- f32x2 packed FMA helpers (sm_100+) ----------------
typedef unsigned long long ull;

__device__ __forceinline__ ull pk2(float x, float y) {
    ull r;
    asm("mov.b64 %0, {%1, %2};" : "=l"(r) : "f"(x), "f"(y));
    return r;
}
__device__ __forceinline__ void ffma2(ull &d, ull a, ull b) {
    asm("fma.rn.f32x2 %0, %1, %2, %0;" : "+l"(d) : "l"(a), "l"(b));
}
__device__ __forceinline__ float fsum2(ull v) {
    float x, y;
    asm("mov.b64 {%0, %1}, %2;" : "=f"(x), "=f"(y) : "l"(v));
    return x + y;
}
__device__ __forceinline__ void upk2(ull v, float &x, float &y) {
    asm("mov.b64 {%0, %1}, %2;" : "=f"(x), "=f"(y) : "l"(v));
}

// ---------------- GAT preprocessing ----------------
__global__ void k_prep(const float* __restrict__ W, const float* __restrict__ as_,
                       const float* __restrict__ ad_) {
    int i = blockIdx.x * blockDim.x + threadIdx.x;
    if (i < Nn) g_deg[i] = 0;
    if (i == 0) {
        float cs = 0.f, cd = 0.f;
        for (int k = 0; k < HIDc; k++) { cs += W[k] * as_[k]; cd += W[k] * ad_[k]; }
        g_cs = cs; g_cd = cd;
    }
}

__global__ void k_deg(const int* __restrict__ ei) {
    int e = blockIdx.x * 256 + threadIdx.x;
    if (e < Ee) atomicAdd(&g_deg[ei[Ee + e]], 1);
}

__global__ void k_scan() {
    __shared__ int s[Nn];
    int i = threadIdx.x;
    int d = g_deg[i];
    s[i] = d;
    __syncthreads();
    for (int off = 1; off < Nn; off <<= 1) {
        int t = 0;
        if (i >= off) t = s[i - off];
        __syncthreads();
        s[i] += t;
        __syncthreads();
    }
    g_off[i] = s[i] - d;
    g_cur[i] = s[i] - d;
}

__global__ void k_fill(const int* __restrict__ ei) {
    int e = blockIdx.x * 256 + threadIdx.x;
    if (e < Ee) {
        int src = ei[e];
        int dst = ei[Ee + e];
        int pos = atomicAdd(&g_cur[dst], 1);
        g_csr[pos] = src;
    }
}

// GAT for batch-0 nodes (the only ones with real incoming edges). One block per t.
__global__ void k_gat_b0(const float* __restrict__ x, const float* __restrict__ W,
                         const float* __restrict__ bias) {
    __shared__ float xs[Nn];
    int t = blockIdx.x;
    int i = threadIdx.x;
    xs[i] = x[t * Nn + i];   // batch 0: (0*T + t)*N + i
    __syncthreads();
    float cs = g_cs, cd = g_cd;
    float xi = xs[i];
    float es = xi * (cs + cd);
    es = es > 0.f ? es : NEG * es;          // self-loop logit
    int beg = g_off[i], end = beg + g_deg[i];
    float m = es;
    for (int e = beg; e < end; e++) {
        float v = cs * xs[g_csr[e]] + cd * xi;
        v = v > 0.f ? v : NEG * v;
        m = fmaxf(m, v);
    }
    float den = expf(es - m);
    float ssum = den * xi;
    for (int e = beg; e < end; e++) {
        float xsrc = xs[g_csr[e]];
        float v = cs * xsrc + cd * xi;
        v = v > 0.f ? v : NEG * v;
        float w = expf(v - m);
        den += w;
        ssum += w * xsrc;
    }
    float s = ssum / den;
    float* o = &g_seq[(size_t)(t * Bb + 0) * Dd + i * HIDc];
#pragma unroll
    for (int k = 0; k < HIDc; k++) {
        float g = fmaf(s, W[k], bias[k]);
        o[k] = g > 0.f ? g : 0.f;
    }
}

// GAT for batches 1..7: self-loop only => s = x
__global__ void k_gat_rest(const float* __restrict__ x, const float* __restrict__ W,
                           const float* __restrict__ bias) {
    int idx = blockIdx.x * 256 + threadIdx.x;
    if (idx >= Tt * (Bb - 1) * Nn) return;
    int t = idx / ((Bb - 1) * Nn);
    int r = idx - t * (Bb - 1) * Nn;
    int b = 1 + (r >> 9);
    int n = r & (Nn - 1);
    float xi = x[((size_t)b * Tt + t) * Nn + n];
    float* o = &g_seq[(size_t)(t * Bb + b) * Dd + n * HIDc];
#pragma unroll
    for (int k = 0; k < HIDc; k++) {
        float g = fmaf(xi, W[k], bias[k]);
        o[k] = g > 0.f ? g : 0.f;
    }
}

// ---------------- input GEMM: Zx[1024,8192] = seq @ w_ih^T + (b_ih+b_hh) ----------------
__global__ void __launch_bounds__(256, 2)
k_zx(const float* __restrict__ Bw, const float* __restrict__ bih,
     const float* __restrict__ bhh) {
    __shared__ __align__(16) float As[16][132];
    __shared__ __align__(16) float Bs[16][132];
    int tid = threadIdx.x;
    int lr = tid >> 2;            // 0..63
    int lk = (tid & 3) * 4;       // 0,4,8,12
    int bm = blockIdx.y * 128;
    int bn = blockIdx.x * 128;
    const float* Ap = g_seq + (size_t)(bm + lr) * Dd + lk;
    const float* Bp = Bw + (size_t)(bn + lr) * Dd + lk;
    int tx = tid & 15, ty = tid >> 4;

    ull acc[8][4];
#pragma unroll
    for (int i = 0; i < 8; i++)
#pragma unroll
        for (int j = 0; j < 4; j++) acc[i][j] = pk2(0.f, 0.f);

    for (int k0 = 0; k0 < Dd; k0 += 16) {
#pragma unroll
        for (int hh = 0; hh < 2; hh++) {
            float4 va = *(const float4*)(Ap + (size_t)hh * 64 * Dd + k0);
            As[lk + 0][lr + hh * 64] = va.x;
            As[lk + 1][lr + hh * 64] = va.y;
            As[lk + 2][lr + hh * 64] = va.z;
            As[lk + 3][lr + hh * 64] = va.w;
            float4 vb = *(const float4*)(Bp + (size_t)hh * 64 * Dd + k0);
            Bs[lk + 0][lr + hh * 64] = vb.x;
            Bs[lk + 1][lr + hh * 64] = vb.y;
            Bs[lk + 2][lr + hh * 64] = vb.z;
            Bs[lk + 3][lr + hh * 64] = vb.w;
        }
        __syncthreads();
#pragma unroll
        for (int kk = 0; kk < 16; kk++) {
            float4 a0 = *(const float4*)(&As[kk][ty * 8]);
            float4 a1 = *(const float4*)(&As[kk][ty * 8 + 4]);
            ulonglong2 b0 = *(const ulonglong2*)(&Bs[kk][tx * 8]);
            ulonglong2 b1 = *(const ulonglong2*)(&Bs[kk][tx * 8 + 4]);
            float av[8] = {a0.x, a0.y, a0.z, a0.w, a1.x, a1.y, a1.z, a1.w};
#pragma unroll
            for (int i = 0; i < 8; i++) {
                ull ad = pk2(av[i], av[i]);
                ffma2(acc[i][0], ad, b0.x);
                ffma2(acc[i][1], ad, b0.y);
                ffma2(acc[i][2], ad, b1.x);
                ffma2(acc[i][3], ad, b1.y);
            }
        }
        __syncthreads();
    }
#pragma unroll
    for (int i = 0; i < 8; i++) {
        int row = bm + ty * 8 + i;
        float* Crow = g_zx + (size_t)row * FD + bn + tx * 8;
#pragma unroll
        for (int jj = 0; jj < 4; jj++) {
            float c0, c1;
            upk2(acc[i][jj], c0, c1);
            int col = bn + tx * 8 + 2 * jj;
            Crow[2 * jj]     = c0 + bih[col]     + bhh[col];
            Crow[2 * jj + 1] = c1 + bih[col + 1] + bhh[col + 1];
        }
    }
}

// ---------------- LSTM init ----------------
__global__ void k_h0() {
    int i = blockIdx.x * 256 + threadIdx.x;
    if (i < Bb * Dd) { g_h[0][i] = 0.f; g_c[i] = 0.f; }
}

// ---------------- one LSTM step (register-blocked, warp K-split) ----------------
// Grid 128 x 512 threads. Block owns d-tile of 16 (64 whh rows = 4 gates x 16).
// Warp wi (0..15): 4 consecutive rows j0..j0+3 where j0 = (wi>>2)*D + d0 + (wi&3)*4.
// Lane = K-split of 32 (64 k per lane, two 1024-chunks).
// Thread computes a 4-row x 8-batch f32x2 register tile; butterfly-reduce over lanes.
__global__ void __launch_bounds__(512, 1)
k_step(const float* __restrict__ whh, int t, int par) {
    // h chunk: [batch][ks(32)][36 pad] -- stride 36 floats => conflict-free LDS.128
    __shared__ __align__(16) float hs[Bb][32][36];
    __shared__ float zbuf[64][9];
    const float* h_in = g_h[par];
    float* h_out = g_h[par ^ 1];
    int tid = threadIdx.x;
    int wi = tid >> 5;
    int lane = tid & 31;
    int d0 = blockIdx.x * 16;
    int g = wi >> 2;
    int ddb = (wi & 3) * 4;
    const float* wr = whh + ((size_t)g * Dd + d0 + ddb) * Dd;   // row j0

    ull acc2[32];
#pragma unroll
    for (int o = 0; o < 32; o++) acc2[o] = 0ull;

    for (int c = 0; c < 2; c++) {
        __syncthreads();
        // cooperative load of h chunk [8][1024] -> swizzled smem
#pragma unroll
        for (int u = 0; u < 4; u++) {
            int fi = tid + u * 512;            // float4 index 0..2047
            int b  = fi >> 8;                  // 256 float4 per batch
            int rem = fi & 255;
            float4 v = *(const float4*)(h_in + (size_t)b * Dd + c * 1024 + rem * 4);
            *(float4*)(&hs[b][rem >> 3][(rem & 7) * 4]) = v;
        }
        __syncthreads();
        const float* wc = wr + c * 1024 + lane * 32;
#pragma unroll
        for (int kk = 0; kk < 32; kk += 4) {
            ulonglong2 wv0 = *(const ulonglong2*)(wc + kk);
            ulonglong2 wv1 = *(const ulonglong2*)(wc + Dd + kk);
            ulonglong2 wv2 = *(const ulonglong2*)(wc + 2 * Dd + kk);
            ulonglong2 wv3 = *(const ulonglong2*)(wc + 3 * Dd + kk);
#pragma unroll
            for (int b = 0; b < Bb; b++) {
                ulonglong2 hv = *(const ulonglong2*)(&hs[b][lane][kk]);
                ffma2(acc2[0 * 8 + b], wv0.x, hv.x);
                ffma2(acc2[0 * 8 + b], wv0.y, hv.y);
                ffma2(acc2[1 * 8 + b], wv1.x, hv.x);
                ffma2(acc2[1 * 8 + b], wv1.y, hv.y);
                ffma2(acc2[2 * 8 + b], wv2.x, hv.x);
                ffma2(acc2[2 * 8 + b], wv2.y, hv.y);
                ffma2(acc2[3 * 8 + b], wv3.x, hv.x);
                ffma2(acc2[3 * 8 + b], wv3.y, hv.y);
            }
        }
    }

    // fold f32x2 halves
    float accf[32];
#pragma unroll
    for (int o = 0; o < 32; o++) accf[o] = fsum2(acc2[o]);

    // butterfly reduction across 32 lanes; halves the per-lane payload each step.
    // Final: lane l holds output o=l (row r=l>>3 of its warp's 4 rows, batch b=l&7).
#define RSTEP(dd, half)                                                     \
    {                                                                       \
        bool hi = (lane & (dd)) != 0;                                       \
        _Pragma("unroll")                                                   \
        for (int i = 0; i < (half); i++) {                                  \
            float mine = accf[hi ? (half) + i : i];                         \
            float send = accf[hi ? i : (half) + i];                         \
            float recv = __shfl_xor_sync(0xffffffffu, send, (dd));          \
            accf[i] = mine + recv;                                          \
        }                                                                   \
    }
    RSTEP(16, 16)
    RSTEP(8, 8)
    RSTEP(4, 4)
    RSTEP(2, 2)
    RSTEP(1, 1)
#undef RSTEP

    // stage z_hh into smem: local row rl = g*16 + ddb + (lane>>3), batch = lane&7
    zbuf[wi * 4 + (lane >> 3)][lane & 7] = accf[0];
    __syncthreads();

    if (tid < 128) {
        int dd2 = tid >> 3;         // 0..15
        int bb = tid & 7;
        const float* zx = g_zx + (size_t)(t * Bb + bb) * FD + d0 + dd2;
        float zi = zbuf[0 * 16 + dd2][bb] + zx[0];
        float zf = zbuf[1 * 16 + dd2][bb] + zx[Dd];
        float zg = zbuf[2 * 16 + dd2][bb] + zx[2 * Dd];
        float zo = zbuf[3 * 16 + dd2][bb] + zx[3 * Dd];
        float ig = 1.f / (1.f + expf(-zi));
        float fg = 1.f / (1.f + expf(-zf));
        float gg = tanhf(zg);
        float og = 1.f / (1.f + expf(-zo));
        int idx = bb * Dd + d0 + dd2;
        float cn = fg * g_c[idx] + ig * gg;
        g_c[idx] = cn;
        h_out[idx] = og * tanhf(cn);
    }
}

// ---------------- final linear: out[8,512] = hT @ w_lin^T + b_lin ----------------
__global__ void k_out(const float* __restrict__ wlin, const float* __restrict__ blin,
                      float* __restrict__ out) {
    int idx = blockIdx.x * 256 + threadIdx.x;
    if (idx >= Bb * Nn) return;
    int bb = idx >> 9;
    int o = idx & 511;
    const float* h = g_h[0] + (size_t)bb * Dd;
    const float* w = wlin + (size_t)o * Dd;
    float acc = 0.f;
    for (int d = 0; d < Dd; d += 4) {
        float4 hv = *(const float4*)(h + d);
        float4 wv = *(const float4*)(w + d);
        acc += hv.x * wv.x + hv.y * wv.y + hv.z * wv.z + hv.w * wv.w;
    }
    out[bb * Nn + o] = acc + blin[o];
}

// ---------------- launch ----------------
extern "C" void kernel_launch(void* const* d_in, const int* in_sizes, int n_in,
                              void* d_out, int out_size) {
    const float* x    = (const float*)d_in[0];
    const float* gw   = (const float*)d_in[1];
    const float* as_  = (const float*)d_in[2];
    const float* ad_  = (const float*)d_in[3];
    const float* gb   = (const float*)d_in[4];
    const float* wih  = (const float*)d_in[5];
    const float* whh  = (const float*)d_in[6];
    const float* bih  = (const float*)d_in[7];
    const float* bhh  = (const float*)d_in[8];
    const float* wlin = (const float*)d_in[9];
    const float* blin = (const float*)d_in[10];
    const int*   ei   = (const int*)d_in[11];
    (void)in_sizes; (void)n_in; (void)out_size;

    // GAT preprocessing + CSR build
    k_prep<<<2, 256>>>(gw, as_, ad_);
    k_deg<<<64, 256>>>(ei);
    k_scan<<<1, 512>>>();
    k_fill<<<64, 256>>>(ei);

    // GAT -> g_seq [1024, 2048]
    k_gat_b0<<<Tt, Nn>>>(x, gw, gb);
    k_gat_rest<<<1792, 256>>>(x, gw, gb);

    // Input projection for all timesteps
    {
        dim3 grid(64, 8);
        k_zx<<<grid, 256>>>(wih, bih, bhh);
    }

    // LSTM recurrence
    k_h0<<<64, 256>>>();
    for (int t = 0; t < Tt; t++) {
        k_step<<<128, 512>>>(whh, t, t & 1);
    }

    // Final linear
    k_out<<<16, 256>>>(wlin, blin, (float*)d_out);
}

// round 4
// speedup vs baseline: 2.1022x; 1.5877x over previous
#include <cuda_runtime.h>
#include <math.h>

// Problem constants
#define Bb   8
#define Tt   128
#define Nn   512
#define HIDc 4
#define Dd   2048
#define Ee   16384
#define FD   8192
#define NEG  0.2f

// ---------------- device scratch (no allocations allowed) ----------------
__device__ __align__(256) float g_seq[1024 * 2048];   // [T*B, D] GAT output, 8 MB
__device__ __align__(256) float g_zx[1024u * 8192u];  // [T*B, 4D] x@Wih^T + bias, 32 MB
__device__ __align__(256) float g_h[2][Bb * Dd];      // double-buffered hidden
__device__ __align__(256) float g_c[Bb * Dd];         // cell state
__device__ int   g_deg[Nn];
__device__ int   g_off[Nn];
__device__ int   g_cur[Nn];
__device__ int   g_csr[Ee];
__device__ float g_cs, g_cd;

// ---------------- f32x2 packed FMA helpers (sm_100+) ----------------
typedef unsigned long long ull;

__device__ __forceinline__ ull pk2(float x, float y) {
    ull r;
    asm("mov.b64 %0, {%1, %2};" : "=l"(r) : "f"(x), "f"(y));
    return r;
}
__device__ __forceinline__ void ffma2(ull &d, ull a, ull b) {
    asm("fma.rn.f32x2 %0, %1, %2, %0;" : "+l"(d) : "l"(a), "l"(b));
}
__device__ __forceinline__ float fsum2(ull v) {
    float x, y;
    asm("mov.b64 {%0, %1}, %2;" : "=f"(x), "=f"(y) : "l"(v));
    return x + y;
}
__device__ __forceinline__ void upk2(ull v, float &x, float &y) {
    asm("mov.b64 {%0, %1}, %2;" : "=f"(x), "=f"(y) : "l"(v));
}

// ---------------- GAT preprocessing ----------------
__global__ void k_prep(const float* __restrict__ W, const float* __restrict__ as_,
                       const float* __restrict__ ad_) {
    int i = blockIdx.x * blockDim.x + threadIdx.x;
    if (i < Nn) g_deg[i] = 0;
    if (i == 0) {
        float cs = 0.f, cd = 0.f;
        for (int k = 0; k < HIDc; k++) { cs += W[k] * as_[k]; cd += W[k] * ad_[k]; }
        g_cs = cs; g_cd = cd;
    }
}

__global__ void k_deg(const int* __restrict__ ei) {
    int e = blockIdx.x * 256 + threadIdx.x;
    if (e < Ee) atomicAdd(&g_deg[ei[Ee + e]], 1);
}

__global__ void k_scan() {
    __shared__ int s[Nn];
    int i = threadIdx.x;
    int d = g_deg[i];
    s[i] = d;
    __syncthreads();
    for (int off = 1; off < Nn; off <<= 1) {
        int t = 0;
        if (i >= off) t = s[i - off];
        __syncthreads();
        s[i] += t;
        __syncthreads();
    }
    g_off[i] = s[i] - d;
    g_cur[i] = s[i] - d;
}

__global__ void k_fill(const int* __restrict__ ei) {
    int e = blockIdx.x * 256 + threadIdx.x;
    if (e < Ee) {
        int src = ei[e];
        int dst = ei[Ee + e];
        int pos = atomicAdd(&g_cur[dst], 1);
        g_csr[pos] = src;
    }
}

// GAT for batch-0 nodes (the only ones with real incoming edges). One block per t.
__global__ void k_gat_b0(const float* __restrict__ x, const float* __restrict__ W,
                         const float* __restrict__ bias) {
    __shared__ float xs[Nn];
    int t = blockIdx.x;
    int i = threadIdx.x;
    xs[i] = x[t * Nn + i];
    __syncthreads();
    float cs = g_cs, cd = g_cd;
    float xi = xs[i];
    float es = xi * (cs + cd);
    es = es > 0.f ? es : NEG * es;
    int beg = g_off[i], end = beg + g_deg[i];
    float m = es;
    for (int e = beg; e < end; e++) {
        float v = cs * xs[g_csr[e]] + cd * xi;
        v = v > 0.f ? v : NEG * v;
        m = fmaxf(m, v);
    }
    float den = expf(es - m);
    float ssum = den * xi;
    for (int e = beg; e < end; e++) {
        float xsrc = xs[g_csr[e]];
        float v = cs * xsrc + cd * xi;
        v = v > 0.f ? v : NEG * v;
        float w = expf(v - m);
        den += w;
        ssum += w * xsrc;
    }
    float s = ssum / den;
    float* o = &g_seq[(size_t)(t * Bb + 0) * Dd + i * HIDc];
#pragma unroll
    for (int k = 0; k < HIDc; k++) {
        float g = fmaf(s, W[k], bias[k]);
        o[k] = g > 0.f ? g : 0.f;
    }
}

// GAT for batches 1..7: self-loop only => s = x
__global__ void k_gat_rest(const float* __restrict__ x, const float* __restrict__ W,
                           const float* __restrict__ bias) {
    int idx = blockIdx.x * 256 + threadIdx.x;
    if (idx >= Tt * (Bb - 1) * Nn) return;
    int t = idx / ((Bb - 1) * Nn);
    int r = idx - t * (Bb - 1) * Nn;
    int b = 1 + (r >> 9);
    int n = r & (Nn - 1);
    float xi = x[((size_t)b * Tt + t) * Nn + n];
    float* o = &g_seq[(size_t)(t * Bb + b) * Dd + n * HIDc];
#pragma unroll
    for (int k = 0; k < HIDc; k++) {
        float g = fmaf(xi, W[k], bias[k]);
        o[k] = g > 0.f ? g : 0.f;
    }
}

// ---------------- input GEMM: Zx[1024,8192] = seq @ w_ih^T + (b_ih+b_hh) ----------------
__global__ void __launch_bounds__(256, 2)
k_zx(const float* __restrict__ Bw, const float* __restrict__ bih,
     const float* __restrict__ bhh) {
    __shared__ __align__(16) float As[16][132];
    __shared__ __align__(16) float Bs[16][132];
    int tid = threadIdx.x;
    int lr = tid >> 2;
    int lk = (tid & 3) * 4;
    int bm = blockIdx.y * 128;
    int bn = blockIdx.x * 128;
    const float* Ap = g_seq + (size_t)(bm + lr) * Dd + lk;
    const float* Bp = Bw + (size_t)(bn + lr) * Dd + lk;
    int tx = tid & 15, ty = tid >> 4;

    ull acc[8][4];
#pragma unroll
    for (int i = 0; i < 8; i++)
#pragma unroll
        for (int j = 0; j < 4; j++) acc[i][j] = pk2(0.f, 0.f);

    for (int k0 = 0; k0 < Dd; k0 += 16) {
#pragma unroll
        for (int hh = 0; hh < 2; hh++) {
            float4 va = *(const float4*)(Ap + (size_t)hh * 64 * Dd + k0);
            As[lk + 0][lr + hh * 64] = va.x;
            As[lk + 1][lr + hh * 64] = va.y;
            As[lk + 2][lr + hh * 64] = va.z;
            As[lk + 3][lr + hh * 64] = va.w;
            float4 vb = *(const float4*)(Bp + (size_t)hh * 64 * Dd + k0);
            Bs[lk + 0][lr + hh * 64] = vb.x;
            Bs[lk + 1][lr + hh * 64] = vb.y;
            Bs[lk + 2][lr + hh * 64] = vb.z;
            Bs[lk + 3][lr + hh * 64] = vb.w;
        }
        __syncthreads();
#pragma unroll
        for (int kk = 0; kk < 16; kk++) {
            float4 a0 = *(const float4*)(&As[kk][ty * 8]);
            float4 a1 = *(const float4*)(&As[kk][ty * 8 + 4]);
            ulonglong2 b0 = *(const ulonglong2*)(&Bs[kk][tx * 8]);
            ulonglong2 b1 = *(const ulonglong2*)(&Bs[kk][tx * 8 + 4]);
            float av[8] = {a0.x, a0.y, a0.z, a0.w, a1.x, a1.y, a1.z, a1.w};
#pragma unroll
            for (int i = 0; i < 8; i++) {
                ull ad = pk2(av[i], av[i]);
                ffma2(acc[i][0], ad, b0.x);
                ffma2(acc[i][1], ad, b0.y);
                ffma2(acc[i][2], ad, b1.x);
                ffma2(acc[i][3], ad, b1.y);
            }
        }
        __syncthreads();
    }
#pragma unroll
    for (int i = 0; i < 8; i++) {
        int row = bm + ty * 8 + i;
        float* Crow = g_zx + (size_t)row * FD + bn + tx * 8;
#pragma unroll
        for (int jj = 0; jj < 4; jj++) {
            float c0, c1;
            upk2(acc[i][jj], c0, c1);
            int col = bn + tx * 8 + 2 * jj;
            Crow[2 * jj]     = c0 + bih[col]     + bhh[col];
            Crow[2 * jj + 1] = c1 + bih[col + 1] + bhh[col + 1];
        }
    }
}

// ---------------- LSTM init ----------------
__global__ void k_h0() {
    int i = blockIdx.x * 256 + threadIdx.x;
    if (i < Bb * Dd) { g_h[0][i] = 0.f; g_c[i] = 0.f; }
}

// ---------------- one LSTM step (register-blocked, lane-contiguous K-split) ----------------
// Grid 128 x 512 threads. Block owns d-tile of 16 (64 whh rows = 4 gates x 16).
// Warp wi: 4 consecutive rows. Lane l owns k in {l*4 + 128*it, it=0..15} (coalesced).
// Thread: 4-row x 8-batch f32x2 register tile; 5-step butterfly reduction over lanes.
__global__ void __launch_bounds__(512, 1)
k_step(const float* __restrict__ whh, int t, int par) {
    __shared__ __align__(16) float hs[Bb][Dd];   // 64 KB, whole h
    __shared__ float zbuf[64][9];
    const float* h_in = g_h[par];
    float* h_out = g_h[par ^ 1];
    int tid = threadIdx.x;
    int wi = tid >> 5;
    int lane = tid & 31;
    int d0 = blockIdx.x * 16;
    int g = wi >> 2;
    int ddb = (wi & 3) * 4;
    const float* wr = whh + ((size_t)g * Dd + d0 + ddb) * Dd + lane * 4;

    // cooperative load of full h [8][2048] = 4096 float4 (512 thr x 8)
#pragma unroll
    for (int u = 0; u < 8; u++) {
        int fi = tid + u * 512;            // float4 index 0..4095
        float4 v = *(const float4*)(h_in + (size_t)fi * 4);
        *(float4*)(&hs[0][0] + (size_t)fi * 4) = v;
    }
    __syncthreads();

    ull acc2[32];
#pragma unroll
    for (int o = 0; o < 32; o++) acc2[o] = 0ull;

    const float* hbase = &hs[0][lane * 4];
#pragma unroll 4
    for (int it = 0; it < 16; it++) {
        int ko = it * 128;
        ulonglong2 wv0 = *(const ulonglong2*)(wr + ko);
        ulonglong2 wv1 = *(const ulonglong2*)(wr + Dd + ko);
        ulonglong2 wv2 = *(const ulonglong2*)(wr + 2 * Dd + ko);
        ulonglong2 wv3 = *(const ulonglong2*)(wr + 3 * Dd + ko);
#pragma unroll
        for (int b = 0; b < Bb; b++) {
            ulonglong2 hv = *(const ulonglong2*)(hbase + b * Dd + ko);
            ffma2(acc2[0 * 8 + b], wv0.x, hv.x);
            ffma2(acc2[0 * 8 + b], wv0.y, hv.y);
            ffma2(acc2[1 * 8 + b], wv1.x, hv.x);
            ffma2(acc2[1 * 8 + b], wv1.y, hv.y);
            ffma2(acc2[2 * 8 + b], wv2.x, hv.x);
            ffma2(acc2[2 * 8 + b], wv2.y, hv.y);
            ffma2(acc2[3 * 8 + b], wv3.x, hv.x);
            ffma2(acc2[3 * 8 + b], wv3.y, hv.y);
        }
    }

    // fold f32x2 halves
    float accf[32];
#pragma unroll
    for (int o = 0; o < 32; o++) accf[o] = fsum2(acc2[o]);

    // butterfly reduction across 32 lanes; halves per-lane payload each step.
    // Final: lane l holds output o=l (row r=l>>3, batch b=l&7).
#define RSTEP(dd, half)                                                     \
    {                                                                       \
        bool hi = (lane & (dd)) != 0;                                       \
        _Pragma("unroll")                                                   \
        for (int i = 0; i < (half); i++) {                                  \
            float mine = accf[hi ? (half) + i : i];                         \
            float send = accf[hi ? i : (half) + i];                         \
            float recv = __shfl_xor_sync(0xffffffffu, send, (dd));          \
            accf[i] = mine + recv;                                          \
        }                                                                   \
    }
    RSTEP(16, 16)
    RSTEP(8, 8)
    RSTEP(4, 4)
    RSTEP(2, 2)
    RSTEP(1, 1)
#undef RSTEP

    zbuf[wi * 4 + (lane >> 3)][lane & 7] = accf[0];
    __syncthreads();

    if (tid < 128) {
        int dd2 = tid >> 3;
        int bb = tid & 7;
        const float* zx = g_zx + (size_t)(t * Bb + bb) * FD + d0 + dd2;
        float zi = zbuf[0 * 16 + dd2][bb] + zx[0];
        float zf = zbuf[1 * 16 + dd2][bb] + zx[Dd];
        float zg = zbuf[2 * 16 + dd2][bb] + zx[2 * Dd];
        float zo = zbuf[3 * 16 + dd2][bb] + zx[3 * Dd];
        float ig = 1.f / (1.f + expf(-zi));
        float fg = 1.f / (1.f + expf(-zf));
        float gg = tanhf(zg);
        float og = 1.f / (1.f + expf(-zo));
        int idx = bb * Dd + d0 + dd2;
        float cn = fg * g_c[idx] + ig * gg;
        g_c[idx] = cn;
        h_out[idx] = og * tanhf(cn);
    }
}

// ---------------- final linear: out[8,512] = hT @ w_lin^T + b_lin ----------------
__global__ void k_out(const float* __restrict__ wlin, const float* __restrict__ blin,
                      float* __restrict__ out) {
    int idx = blockIdx.x * 256 + threadIdx.x;
    if (idx >= Bb * Nn) return;
    int bb = idx >> 9;
    int o = idx & 511;
    const float* h = g_h[0] + (size_t)bb * Dd;
    const float* w = wlin + (size_t)o * Dd;
    float acc = 0.f;
    for (int d = 0; d < Dd; d += 4) {
        float4 hv = *(const float4*)(h + d);
        float4 wv = *(const float4*)(w + d);
        acc += hv.x * wv.x + hv.y * wv.y + hv.z * wv.z + hv.w * wv.w;
    }
    out[bb * Nn + o] = acc + blin[o];
}

// ---------------- launch ----------------
extern "C" void kernel_launch(void* const* d_in, const int* in_sizes, int n_in,
                              void* d_out, int out_size) {
    const float* x    = (const float*)d_in[0];
    const float* gw   = (const float*)d_in[1];
    const float* as_  = (const float*)d_in[2];
    const float* ad_  = (const float*)d_in[3];
    const float* gb   = (const float*)d_in[4];
    const float* wih  = (const float*)d_in[5];
    const float* whh  = (const float*)d_in[6];
    const float* bih  = (const float*)d_in[7];
    const float* bhh  = (const float*)d_in[8];
    const float* wlin = (const float*)d_in[9];
    const float* blin = (const float*)d_in[10];
    const int*   ei   = (const int*)d_in[11];
    (void)in_sizes; (void)n_in; (void)out_size;

    // GAT preprocessing + CSR build
    k_prep<<<2, 256>>>(gw, as_, ad_);
    k_deg<<<64, 256>>>(ei);
    k_scan<<<1, 512>>>();
    k_fill<<<64, 256>>>(ei);

    // GAT -> g_seq [1024, 2048]
    k_gat_b0<<<Tt, Nn>>>(x, gw, gb);
    k_gat_rest<<<1792, 256>>>(x, gw, gb);

    // Input projection for all timesteps
    {
        dim3 grid(64, 8);
        k_zx<<<grid, 256>>>(wih, bih, bhh);
    }

    // LSTM recurrence
    k_h0<<<64, 256>>>();
    for (int t = 0; t < Tt; t++) {
        k_step<<<128, 512>>>(whh, t, t & 1);
    }

    // Final linear
    k_out<<<16, 256>>>(wlin, blin, (float*)d_out);
}

// round 5
// speedup vs baseline: 2.2559x; 1.0731x over previous
#include <cuda_runtime.h>
#include <math.h>

// Problem constants
#define Bb   8
#define Tt   128
#define Nn   512
#define HIDc 4
#define Dd   2048
#define Ee   16384
#define FD   8192
#define NEG  0.2f

// ---------------- device scratch (no allocations allowed) ----------------
__device__ __align__(256) float g_seq[1024 * 2048];   // [T*B, D] GAT output, 8 MB
__device__ __align__(256) float g_zx[1024u * 8192u];  // [T*B, 4D] x@Wih^T + bias, 32 MB
__device__ __align__(256) float g_h[2][Bb * Dd];      // double-buffered hidden
__device__ int   g_bar[Tt];                            // per-step grid barrier counters
__device__ int   g_deg[Nn];
__device__ int   g_off[Nn];
__device__ int   g_cur[Nn];
__device__ int   g_csr[Ee];
__device__ float g_cs, g_cd;

// ---------------- f32x2 packed FMA helpers (sm_100+) ----------------
typedef unsigned long long ull;

__device__ __forceinline__ ull pk2(float x, float y) {
    ull r;
    asm("mov.b64 %0, {%1, %2};" : "=l"(r) : "f"(x), "f"(y));
    return r;
}
__device__ __forceinline__ void ffma2(ull &d, ull a, ull b) {
    asm("fma.rn.f32x2 %0, %1, %2, %0;" : "+l"(d) : "l"(a), "l"(b));
}
__device__ __forceinline__ float fsum2(ull v) {
    float x, y;
    asm("mov.b64 {%0, %1}, %2;" : "=f"(x), "=f"(y) : "l"(v));
    return x + y;
}
__device__ __forceinline__ void upk2(ull v, float &x, float &y) {
    asm("mov.b64 {%0, %1}, %2;" : "=f"(x), "=f"(y) : "l"(v));
}

// ---------------- GAT preprocessing ----------------
__global__ void k_prep(const float* __restrict__ W, const float* __restrict__ as_,
                       const float* __restrict__ ad_) {
    int i = blockIdx.x * blockDim.x + threadIdx.x;
    if (i < Nn) g_deg[i] = 0;
    if (i < Tt) g_bar[i] = 0;              // clear grid-barrier counters each call
    if (i == 0) {
        float cs = 0.f, cd = 0.f;
        for (int k = 0; k < HIDc; k++) { cs += W[k] * as_[k]; cd += W[k] * ad_[k]; }
        g_cs = cs; g_cd = cd;
    }
}

__global__ void k_deg(const int* __restrict__ ei) {
    int e = blockIdx.x * 256 + threadIdx.x;
    if (e < Ee) atomicAdd(&g_deg[ei[Ee + e]], 1);
}

__global__ void k_scan() {
    __shared__ int s[Nn];
    int i = threadIdx.x;
    int d = g_deg[i];
    s[i] = d;
    __syncthreads();
    for (int off = 1; off < Nn; off <<= 1) {
        int t = 0;
        if (i >= off) t = s[i - off];
        __syncthreads();
        s[i] += t;
        __syncthreads();
    }
    g_off[i] = s[i] - d;
    g_cur[i] = s[i] - d;
}

__global__ void k_fill(const int* __restrict__ ei) {
    int e = blockIdx.x * 256 + threadIdx.x;
    if (e < Ee) {
        int src = ei[e];
        int dst = ei[Ee + e];
        int pos = atomicAdd(&g_cur[dst], 1);
        g_csr[pos] = src;
    }
}

// GAT for batch-0 nodes (the only ones with real incoming edges). One block per t.
__global__ void k_gat_b0(const float* __restrict__ x, const float* __restrict__ W,
                         const float* __restrict__ bias) {
    __shared__ float xs[Nn];
    int t = blockIdx.x;
    int i = threadIdx.x;
    xs[i] = x[t * Nn + i];
    __syncthreads();
    float cs = g_cs, cd = g_cd;
    float xi = xs[i];
    float es = xi * (cs + cd);
    es = es > 0.f ? es : NEG * es;
    int beg = g_off[i], end = beg + g_deg[i];
    float m = es;
    for (int e = beg; e < end; e++) {
        float v = cs * xs[g_csr[e]] + cd * xi;
        v = v > 0.f ? v : NEG * v;
        m = fmaxf(m, v);
    }
    float den = expf(es - m);
    float ssum = den * xi;
    for (int e = beg; e < end; e++) {
        float xsrc = xs[g_csr[e]];
        float v = cs * xsrc + cd * xi;
        v = v > 0.f ? v : NEG * v;
        float w = expf(v - m);
        den += w;
        ssum += w * xsrc;
    }
    float s = ssum / den;
    float* o = &g_seq[(size_t)(t * Bb + 0) * Dd + i * HIDc];
#pragma unroll
    for (int k = 0; k < HIDc; k++) {
        float g = fmaf(s, W[k], bias[k]);
        o[k] = g > 0.f ? g : 0.f;
    }
}

// GAT for batches 1..7: self-loop only => s = x
__global__ void k_gat_rest(const float* __restrict__ x, const float* __restrict__ W,
                           const float* __restrict__ bias) {
    int idx = blockIdx.x * 256 + threadIdx.x;
    if (idx >= Tt * (Bb - 1) * Nn) return;
    int t = idx / ((Bb - 1) * Nn);
    int r = idx - t * (Bb - 1) * Nn;
    int b = 1 + (r >> 9);
    int n = r & (Nn - 1);
    float xi = x[((size_t)b * Tt + t) * Nn + n];
    float* o = &g_seq[(size_t)(t * Bb + b) * Dd + n * HIDc];
#pragma unroll
    for (int k = 0; k < HIDc; k++) {
        float g = fmaf(xi, W[k], bias[k]);
        o[k] = g > 0.f ? g : 0.f;
    }
}

// ---------------- input GEMM: Zx[1024,8192] = seq @ w_ih^T + (b_ih+b_hh) ----------------
__global__ void __launch_bounds__(256, 2)
k_zx(const float* __restrict__ Bw, const float* __restrict__ bih,
     const float* __restrict__ bhh) {
    __shared__ __align__(16) float As[16][132];
    __shared__ __align__(16) float Bs[16][132];
    int tid = threadIdx.x;
    int lr = tid >> 2;
    int lk = (tid & 3) * 4;
    int bm = blockIdx.y * 128;
    int bn = blockIdx.x * 128;
    const float* Ap = g_seq + (size_t)(bm + lr) * Dd + lk;
    const float* Bp = Bw + (size_t)(bn + lr) * Dd + lk;
    int tx = tid & 15, ty = tid >> 4;

    ull acc[8][4];
#pragma unroll
    for (int i = 0; i < 8; i++)
#pragma unroll
        for (int j = 0; j < 4; j++) acc[i][j] = pk2(0.f, 0.f);

    for (int k0 = 0; k0 < Dd; k0 += 16) {
#pragma unroll
        for (int hh = 0; hh < 2; hh++) {
            float4 va = *(const float4*)(Ap + (size_t)hh * 64 * Dd + k0);
            As[lk + 0][lr + hh * 64] = va.x;
            As[lk + 1][lr + hh * 64] = va.y;
            As[lk + 2][lr + hh * 64] = va.z;
            As[lk + 3][lr + hh * 64] = va.w;
            float4 vb = *(const float4*)(Bp + (size_t)hh * 64 * Dd + k0);
            Bs[lk + 0][lr + hh * 64] = vb.x;
            Bs[lk + 1][lr + hh * 64] = vb.y;
            Bs[lk + 2][lr + hh * 64] = vb.z;
            Bs[lk + 3][lr + hh * 64] = vb.w;
        }
        __syncthreads();
#pragma unroll
        for (int kk = 0; kk < 16; kk++) {
            float4 a0 = *(const float4*)(&As[kk][ty * 8]);
            float4 a1 = *(const float4*)(&As[kk][ty * 8 + 4]);
            ulonglong2 b0 = *(const ulonglong2*)(&Bs[kk][tx * 8]);
            ulonglong2 b1 = *(const ulonglong2*)(&Bs[kk][tx * 8 + 4]);
            float av[8] = {a0.x, a0.y, a0.z, a0.w, a1.x, a1.y, a1.z, a1.w};
#pragma unroll
            for (int i = 0; i < 8; i++) {
                ull ad = pk2(av[i], av[i]);
                ffma2(acc[i][0], ad, b0.x);
                ffma2(acc[i][1], ad, b0.y);
                ffma2(acc[i][2], ad, b1.x);
                ffma2(acc[i][3], ad, b1.y);
            }
        }
        __syncthreads();
    }
#pragma unroll
    for (int i = 0; i < 8; i++) {
        int row = bm + ty * 8 + i;
        float* Crow = g_zx + (size_t)row * FD + bn + tx * 8;
#pragma unroll
        for (int jj = 0; jj < 4; jj++) {
            float c0, c1;
            upk2(acc[i][jj], c0, c1);
            int col = bn + tx * 8 + 2 * jj;
            Crow[2 * jj]     = c0 + bih[col]     + bhh[col];
            Crow[2 * jj + 1] = c1 + bih[col + 1] + bhh[col + 1];
        }
    }
}

// ---------------- persistent LSTM: all 128 steps + final linear ----------------
// Grid 128 x 512 (single wave, all blocks co-resident => software grid barrier OK).
// Block bid owns d-tile [bid*16, bid*16+16): computes 64 whh rows (4 gates x 16),
// keeps its c-slice in smem, writes its h-slice, barriers, reloads full h.
// After step 127: block computes out cols [bid*4, bid*4+4).
__global__ void __launch_bounds__(512, 1)
k_lstm(const float* __restrict__ whh, const float* __restrict__ wlin,
       const float* __restrict__ blin, float* __restrict__ out) {
    __shared__ __align__(16) float hs[Bb][Dd];   // 64 KB: full h
    __shared__ float zbuf[64][9];
    __shared__ float cs_[128];                   // c slice: [b*16 + dd]
    int tid = threadIdx.x;
    int wi = tid >> 5;
    int lane = tid & 31;
    int bid = blockIdx.x;
    int d0 = bid * 16;
    int g = wi >> 2;
    int ddb = (wi & 3) * 4;
    const float* wr = whh + ((size_t)g * Dd + d0 + ddb) * Dd + lane * 4;

    // h_0 = 0 in smem, c = 0
#pragma unroll
    for (int u = 0; u < 8; u++) {
        int fi = tid + u * 512;
        *(float4*)(&hs[0][0] + (size_t)fi * 4) = make_float4(0.f, 0.f, 0.f, 0.f);
    }
    if (tid < 128) cs_[tid] = 0.f;
    __syncthreads();

    for (int t = 0; t < Tt; t++) {
        if (t > 0) {
            const float* h_in = g_h[t & 1];
#pragma unroll
            for (int u = 0; u < 8; u++) {
                int fi = tid + u * 512;
                float4 v = *(const float4*)(h_in + (size_t)fi * 4);
                *(float4*)(&hs[0][0] + (size_t)fi * 4) = v;
            }
            __syncthreads();
        }

        ull acc2[32];
#pragma unroll
        for (int o = 0; o < 32; o++) acc2[o] = 0ull;

        const float* hbase = &hs[0][lane * 4];
#pragma unroll 4
        for (int it = 0; it < 16; it++) {
            int ko = it * 128;
            ulonglong2 wv0 = *(const ulonglong2*)(wr + ko);
            ulonglong2 wv1 = *(const ulonglong2*)(wr + Dd + ko);
            ulonglong2 wv2 = *(const ulonglong2*)(wr + 2 * Dd + ko);
            ulonglong2 wv3 = *(const ulonglong2*)(wr + 3 * Dd + ko);
#pragma unroll
            for (int b = 0; b < Bb; b++) {
                ulonglong2 hv = *(const ulonglong2*)(hbase + b * Dd + ko);
                ffma2(acc2[0 * 8 + b], wv0.x, hv.x);
                ffma2(acc2[0 * 8 + b], wv0.y, hv.y);
                ffma2(acc2[1 * 8 + b], wv1.x, hv.x);
                ffma2(acc2[1 * 8 + b], wv1.y, hv.y);
                ffma2(acc2[2 * 8 + b], wv2.x, hv.x);
                ffma2(acc2[2 * 8 + b], wv2.y, hv.y);
                ffma2(acc2[3 * 8 + b], wv3.x, hv.x);
                ffma2(acc2[3 * 8 + b], wv3.y, hv.y);
            }
        }

        float accf[32];
#pragma unroll
        for (int o = 0; o < 32; o++) accf[o] = fsum2(acc2[o]);

        // 5-step butterfly reduction; lane l ends holding output (row l>>3, batch l&7)
#define RSTEP(dd, half)                                                     \
        {                                                                   \
            bool hi = (lane & (dd)) != 0;                                   \
            _Pragma("unroll")                                               \
            for (int i = 0; i < (half); i++) {                              \
                float mine = accf[hi ? (half) + i : i];                     \
                float send = accf[hi ? i : (half) + i];                     \
                float recv = __shfl_xor_sync(0xffffffffu, send, (dd));      \
                accf[i] = mine + recv;                                      \
            }                                                               \
        }
        RSTEP(16, 16)
        RSTEP(8, 8)
        RSTEP(4, 4)
        RSTEP(2, 2)
        RSTEP(1, 1)
#undef RSTEP

        zbuf[wi * 4 + (lane >> 3)][lane & 7] = accf[0];
        __syncthreads();

        if (tid < 128) {
            int dd2 = tid >> 3;
            int bb = tid & 7;
            const float* zx = g_zx + (size_t)(t * Bb + bb) * FD + d0 + dd2;
            float zi = zbuf[0 * 16 + dd2][bb] + zx[0];
            float zf = zbuf[1 * 16 + dd2][bb] + zx[Dd];
            float zg = zbuf[2 * 16 + dd2][bb] + zx[2 * Dd];
            float zo = zbuf[3 * 16 + dd2][bb] + zx[3 * Dd];
            float ig = 1.f / (1.f + expf(-zi));
            float fg = 1.f / (1.f + expf(-zf));
            float gg = tanhf(zg);
            float og = 1.f / (1.f + expf(-zo));
            float cn = fg * cs_[bb * 16 + dd2] + ig * gg;
            cs_[bb * 16 + dd2] = cn;
            g_h[(t + 1) & 1][bb * Dd + d0 + dd2] = og * tanhf(cn);
        }
        __syncthreads();

        // grid barrier for step t
        if (tid == 0) {
            __threadfence();
            atomicAdd(&g_bar[t], 1);
            while (*(volatile int*)&g_bar[t] < 128) { }
            __threadfence();
        }
        __syncthreads();
    }

    // final linear: h_T is in g_h[0] (t=127 wrote (127+1)&1 = 0).
    // 16 warps: col = bid*4 + (wi&3), batch pair p = wi>>2 -> batches {2p, 2p+1}
    {
        int col = bid * 4 + (wi & 3);
        int p = wi >> 2;
        const float* wl = wlin + (size_t)col * Dd + lane * 4;
        const float* h0 = g_h[0] + (size_t)(2 * p) * Dd + lane * 4;
        const float* h1 = g_h[0] + (size_t)(2 * p + 1) * Dd + lane * 4;
        ull s0 = 0ull, s1 = 0ull;
#pragma unroll 4
        for (int it = 0; it < 16; it++) {
            int ko = it * 128;
            ulonglong2 wv = *(const ulonglong2*)(wl + ko);
            ulonglong2 hv0 = *(const ulonglong2*)(h0 + ko);
            ulonglong2 hv1 = *(const ulonglong2*)(h1 + ko);
            ffma2(s0, wv.x, hv0.x);
            ffma2(s0, wv.y, hv0.y);
            ffma2(s1, wv.x, hv1.x);
            ffma2(s1, wv.y, hv1.y);
        }
        float f0 = fsum2(s0), f1 = fsum2(s1);
#pragma unroll
        for (int d = 16; d; d >>= 1) {
            f0 += __shfl_xor_sync(0xffffffffu, f0, d);
            f1 += __shfl_xor_sync(0xffffffffu, f1, d);
        }
        if (lane == 0) {
            float bl = blin[col];
            out[(2 * p) * Nn + col]     = f0 + bl;
            out[(2 * p + 1) * Nn + col] = f1 + bl;
        }
    }
}

// ---------------- launch ----------------
extern "C" void kernel_launch(void* const* d_in, const int* in_sizes, int n_in,
                              void* d_out, int out_size) {
    const float* x    = (const float*)d_in[0];
    const float* gw   = (const float*)d_in[1];
    const float* as_  = (const float*)d_in[2];
    const float* ad_  = (const float*)d_in[3];
    const float* gb   = (const float*)d_in[4];
    const float* wih  = (const float*)d_in[5];
    const float* whh  = (const float*)d_in[6];
    const float* bih  = (const float*)d_in[7];
    const float* bhh  = (const float*)d_in[8];
    const float* wlin = (const float*)d_in[9];
    const float* blin = (const float*)d_in[10];
    const int*   ei   = (const int*)d_in[11];
    (void)in_sizes; (void)n_in; (void)out_size;

    // GAT preprocessing + CSR build (also clears grid-barrier counters)
    k_prep<<<2, 256>>>(gw, as_, ad_);
    k_deg<<<64, 256>>>(ei);
    k_scan<<<1, 512>>>();
    k_fill<<<64, 256>>>(ei);

    // GAT -> g_seq [1024, 2048]
    k_gat_b0<<<Tt, Nn>>>(x, gw, gb);
    k_gat_rest<<<1792, 256>>>(x, gw, gb);

    // Input projection for all timesteps
    {
        dim3 grid(64, 8);
        k_zx<<<grid, 256>>>(wih, bih, bhh);
    }

    // Persistent LSTM (all steps) + final linear
    k_lstm<<<128, 512>>>(whh, wlin, blin, (float*)d_out);
}